// round 14
// baseline (speedup 1.0000x reference)
#include <cuda_runtime.h>

// Problem constants
#define Nn 100000
#define Ee 200000
#define Gg 2500
#define FN 16
#define FE 8
#define H1c 32
#define H2c 16
#define EBLK 1563   // ceil(Ee/128)
#define ABLK 782    // ceil(Nn/128)

typedef unsigned long long u64;

// ---- packed f32x2 helpers (sm_103a FFMA2 path) --------------------------------
__device__ __forceinline__ u64 pk2(float v) {
    u64 r; asm("mov.b64 %0, {%1, %1};" : "=l"(r) : "r"(__float_as_uint(v)));
    return r;
}
__device__ __forceinline__ void fma2(u64& d, u64 a, u64 b) {
    asm("fma.rn.f32x2 %0, %1, %2, %0;" : "+l"(d) : "l"(a), "l"(b));
}
__device__ __forceinline__ u64 add2(u64 a, u64 b) {
    u64 r; asm("add.rn.f32x2 %0, %1, %2;" : "=l"(r) : "l"(a), "l"(b));
    return r;
}
__device__ __forceinline__ void upk(u64 v, float& lo, float& hi) {
    unsigned a, b;
    asm("mov.b64 {%0, %1}, %2;" : "=r"(a), "=r"(b) : "l"(v));
    lo = __uint_as_float(a); hi = __uint_as_float(b);
}

// ---------------- scratch (device globals; no allocation allowed) -------------
__device__ float    g_gate[Nn];      // stores exp(gate) (no max-shift; gates O(0.3))
__device__ float    g_s[Gg];
__device__ float    g_num[Gg * FN];
__device__ float    g_cnt[Gg];
__device__ float    g_agg1[Nn * H1c];
__device__ float    g_h1[Nn * H1c];
__device__ float    g_agg2[Nn * H2c];
__device__ float    g_h2sum[Gg * H2c];

// ------ gate (stores exp) + zero node aggs + zero graph scratch (low gids) ----
__global__ void k_gate(const float* __restrict__ x,
                       const float* __restrict__ wg1, const float* __restrict__ bg1,
                       const float* __restrict__ wg2, const float* __restrict__ bg2) {
    __shared__ float sw1[FN * FN], sb1[FN], sw2[FN], sb2;
    int tid = threadIdx.x;
    if (tid < FN * FN) sw1[tid] = wg1[tid];
    if (tid < FN) { sb1[tid] = bg1[tid]; sw2[tid] = wg2[tid]; }
    if (tid == 0) sb2 = bg2[0];
    __syncthreads();
    int n = blockIdx.x * blockDim.x + tid;
    // zero per-graph scratch (consumed only by LATER kernels; boundary orders it)
    if (n < Gg) { g_s[n] = 0.f; g_cnt[n] = 0.f; }
    if (n < Gg * FN) g_num[n] = 0.f;
    if (n < Gg * H2c) g_h2sum[n] = 0.f;
    if (n >= Nn) return;
    // zero this node's aggregation rows
    float4 z4 = make_float4(0.f, 0.f, 0.f, 0.f);
    float4* a1 = (float4*)(&g_agg1[n * H1c]);
    float4* a2 = (float4*)(&g_agg2[n * H2c]);
#pragma unroll
    for (int r = 0; r < H1c / 4; r++) a1[r] = z4;
#pragma unroll
    for (int r = 0; r < H2c / 4; r++) a2[r] = z4;

    float xv[FN];
#pragma unroll
    for (int i = 0; i < FN; i++) xv[i] = x[n * FN + i];
    float g = sb2;
#pragma unroll
    for (int j = 0; j < FN; j++) {
        float h = sb1[j];
#pragma unroll
        for (int i = 0; i < FN; i++) h += xv[i] * sw1[i * FN + j];
        g += fmaxf(h, 0.f) * sw2[j];
    }
    g_gate[n] = expf(g);   // softmax is shift-invariant; no max-shift needed
}

// ---------------- fused: conv1 (blocks [0,EBLK)) + att (blocks [EBLK,..)) -----
__global__ void __launch_bounds__(128) k_fused1(
        const float* __restrict__ x, const float* __restrict__ ea,
        const float* __restrict__ w_e1a, const float* __restrict__ b_e1a,
        const float* __restrict__ w_e1b, const float* __restrict__ b_e1b,
        const int* __restrict__ ei, const int* __restrict__ batch) {
    __shared__ float4 sw4[16 * 16 * 8];   // w_e1b [k][i][o4]
    __shared__ float4 sbb4[16 * 8];       // b_e1b [i][o4]
    __shared__ float4 swa4[FE * 4];
    __shared__ float  sba[16];
    __shared__ float  sh[16][128];        // h[k][edge-slot]
    int tid = threadIdx.x;

    if (blockIdx.x >= EBLK) {
        // ---------------- attention-softmax accumulation path ----------------
        int n = (blockIdx.x - EBLK) * 128 + tid;
        bool valid = n < Nn;
        int b = valid ? batch[n] : -1;
        float a = 0.f;
        float xs[FN];
#pragma unroll
        for (int f = 0; f < FN; f++) xs[f] = 0.f;
        if (valid) {
            a = g_gate[n];   // already exp(gate)
            const float4* xp = (const float4*)(x + n * FN);
#pragma unroll
            for (int r = 0; r < 4; r++) {
                float4 v = xp[r];
                xs[r*4+0]=v.x; xs[r*4+1]=v.y; xs[r*4+2]=v.z; xs[r*4+3]=v.w;
            }
        }
        const unsigned m = 0xffffffffu;
        int b0 = __shfl_sync(m, b, 0);
        if (__all_sync(m, valid && (b == b0))) {
            float sa = a;
            float v[FN];
#pragma unroll
            for (int f = 0; f < FN; f++) v[f] = a * xs[f];
#pragma unroll
            for (int d = 16; d; d >>= 1) {
                sa += __shfl_xor_sync(m, sa, d);
#pragma unroll
                for (int f = 0; f < FN; f++) v[f] += __shfl_xor_sync(m, v[f], d);
            }
            if ((tid & 31) == 0) {
                atomicAdd(&g_s[b0], sa);
                atomicAdd(&g_cnt[b0], 32.f);
#pragma unroll
                for (int f = 0; f < FN; f++) atomicAdd(&g_num[b0 * FN + f], v[f]);
            }
        } else if (valid) {
            atomicAdd(&g_s[b], a);
            atomicAdd(&g_cnt[b], 1.f);
#pragma unroll
            for (int f = 0; f < FN; f++)
                atomicAdd(&g_num[b * FN + f], a * xs[f]);
        }
        return;
    }

    // ---------------- conv1 path: 4 edges / 4-thread group, o-quarter --------
    for (int t = tid; t < 16 * 16 * 8; t += 128) sw4[t] = ((const float4*)w_e1b)[t];
    for (int t = tid; t < 16 * 8;      t += 128) sbb4[t] = ((const float4*)b_e1b)[t];
    if (tid < FE * 4) swa4[tid] = ((const float4*)w_e1a)[tid];
    if (tid < 16) sba[tid] = b_e1a[tid];
    __syncthreads();

    int eBase = blockIdx.x * 128;
    int myE = eBase + tid;
    if (myE < Ee) {
        const float4* eap = (const float4*)(ea + myE * FE);
        float4 a0 = eap[0], a1 = eap[1];
        float eav[FE] = {a0.x,a0.y,a0.z,a0.w,a1.x,a1.y,a1.z,a1.w};
        float hv[16];
#pragma unroll
        for (int l = 0; l < 16; l++) hv[l] = sba[l];
#pragma unroll
        for (int j = 0; j < FE; j++) {
            float c = eav[j];
#pragma unroll
            for (int l4 = 0; l4 < 4; l4++) {
                float4 w = swa4[j * 4 + l4];
                hv[l4*4+0] += c * w.x; hv[l4*4+1] += c * w.y;
                hv[l4*4+2] += c * w.z; hv[l4*4+3] += c * w.w;
            }
        }
#pragma unroll
        for (int l = 0; l < 16; l++) sh[l][tid] = fmaxf(hv[l], 0.f);
    } else {
#pragma unroll
        for (int l = 0; l < 16; l++) sh[l][tid] = 0.f;
    }
    __syncwarp();

    int q = tid & 3;          // o-quarter
    int base = tid & ~3;

    float xv[4][16];
#pragma unroll
    for (int j = 0; j < 4; j++) {
        int e = eBase + base + j;
        int src = (e < Ee) ? ei[e] : 0;
        const float4* p = (const float4*)(x + src * FN);
#pragma unroll
        for (int r = 0; r < 4; r++) {
            float4 v = p[r];
            xv[j][r*4+0]=v.x; xv[j][r*4+1]=v.y; xv[j][r*4+2]=v.z; xv[j][r*4+3]=v.w;
        }
    }

    u64 acc2[4][4];   // [edge][o-pair], packed (o, o+1)
#pragma unroll
    for (int j = 0; j < 4; j++)
#pragma unroll
        for (int p = 0; p < 4; p++) acc2[j][p] = 0ull;

    // bias term
#pragma unroll
    for (int i = 0; i < 16; i++) {
        const ulonglong2* bw = (const ulonglong2*)&sbb4[i * 8 + q * 2];
        ulonglong2 ua = bw[0], ub = bw[1];
#pragma unroll
        for (int j = 0; j < 4; j++) {
            u64 cc = pk2(xv[j][i]);
            fma2(acc2[j][0], ua.x, cc); fma2(acc2[j][1], ua.y, cc);
            fma2(acc2[j][2], ub.x, cc); fma2(acc2[j][3], ub.y, cc);
        }
    }
    // main term: hk via one LDS.128 (sh row is 16B-aligned at base)
#pragma unroll 1
    for (int k = 0; k < 16; k++) {
        float4 hk4 = *(const float4*)&sh[k][base];
        float hk[4] = {hk4.x, hk4.y, hk4.z, hk4.w};
        const float4* wk = &sw4[k * 128 + q * 2];
#pragma unroll
        for (int i = 0; i < 16; i++) {
            const ulonglong2* wp = (const ulonglong2*)&wk[i * 8];
            ulonglong2 ua = wp[0], ub = wp[1];
#pragma unroll
            for (int j = 0; j < 4; j++) {
                u64 cc = pk2(hk[j] * xv[j][i]);
                fma2(acc2[j][0], ua.x, cc); fma2(acc2[j][1], ua.y, cc);
                fma2(acc2[j][2], ub.x, cc); fma2(acc2[j][3], ub.y, cc);
            }
        }
    }
    // targets loaded AFTER the mainloop (keeps them out of loop liveness)
#pragma unroll
    for (int j = 0; j < 4; j++) {
        int e = eBase + base + j;
        if (e >= Ee) continue;
        int tgt = ei[Ee + e];
        float* dst = &g_agg1[tgt * H1c + q * 8];
#pragma unroll
        for (int p = 0; p < 4; p++) {
            float lo, hi; upk(acc2[j][p], lo, hi);
            atomicAdd(dst + 2 * p + 0, lo);
            atomicAdd(dst + 2 * p + 1, hi);
        }
    }
}

// ---------------- node1: 2 threads per node (o-half) --------------------------
__global__ void __launch_bounds__(256) k_node1(
        const float* __restrict__ x,
        const float* __restrict__ wr, const float* __restrict__ br) {
    __shared__ float sw[FN * H1c], sb[H1c];
    int tid = threadIdx.x;
    for (int t = tid; t < FN * H1c; t += blockDim.x) sw[t] = wr[t];
    if (tid < H1c) sb[tid] = br[tid];
    __syncthreads();
    int gid = blockIdx.x * blockDim.x + tid;
    int n = gid >> 1, h = gid & 1;
    if (n >= Nn) return;
    float xv[FN];
    {
        const float4* xp = (const float4*)(x + n * FN);
#pragma unroll
        for (int r = 0; r < 4; r++) {
            float4 v = xp[r];
            xv[r*4+0]=v.x; xv[r*4+1]=v.y; xv[r*4+2]=v.z; xv[r*4+3]=v.w;
        }
    }
    float acc[16];
    {
        const float4* ap = (const float4*)(&g_agg1[n * H1c + h * 16]);
#pragma unroll
        for (int r = 0; r < 4; r++) {
            float4 v = ap[r];
            acc[r*4+0]=v.x; acc[r*4+1]=v.y; acc[r*4+2]=v.z; acc[r*4+3]=v.w;
        }
    }
#pragma unroll
    for (int o = 0; o < 16; o++) {
        float v = acc[o] + sb[h * 16 + o];
#pragma unroll
        for (int i = 0; i < FN; i++) v += xv[i] * sw[i * H1c + h * 16 + o];
        acc[o] = fmaxf(v, 0.f);
    }
    float4* hp = (float4*)(&g_h1[n * H1c + h * 16]);
#pragma unroll
    for (int r = 0; r < 4; r++)
        hp[r] = make_float4(acc[r*4+0], acc[r*4+1], acc[r*4+2], acc[r*4+3]);
}

// ---------------- conv2: 4 edges / 4-thread group, (i-half x o-half), FFMA2 ---
__global__ void __launch_bounds__(128) k_conv2(
        const float* __restrict__ ea,
        const float* __restrict__ w_e2a, const float* __restrict__ b_e2a,
        const float* __restrict__ w_e2b, const float* __restrict__ b_e2b,
        const int* __restrict__ ei) {
    __shared__ float4 sw4[16 * 32 * 4];   // w_e2b [k][i][o4]
    __shared__ float4 sbb4[32 * 4];       // b_e2b [i][o4]
    __shared__ float4 swa4[FE * 4];
    __shared__ float  sba[16];
    __shared__ float  sh[16][128];
    int tid = threadIdx.x;
    for (int t = tid; t < 16 * 32 * 4; t += 128) sw4[t] = ((const float4*)w_e2b)[t];
    for (int t = tid; t < 32 * 4;      t += 128) sbb4[t] = ((const float4*)b_e2b)[t];
    if (tid < FE * 4) swa4[tid] = ((const float4*)w_e2a)[tid];
    if (tid < 16) sba[tid] = b_e2a[tid];
    __syncthreads();

    int eBase = blockIdx.x * 128;
    int myE = eBase + tid;
    if (myE < Ee) {
        const float4* eap = (const float4*)(ea + myE * FE);
        float4 a0 = eap[0], a1 = eap[1];
        float eav[FE] = {a0.x,a0.y,a0.z,a0.w,a1.x,a1.y,a1.z,a1.w};
        float hv[16];
#pragma unroll
        for (int l = 0; l < 16; l++) hv[l] = sba[l];
#pragma unroll
        for (int j = 0; j < FE; j++) {
            float c = eav[j];
#pragma unroll
            for (int l4 = 0; l4 < 4; l4++) {
                float4 w = swa4[j * 4 + l4];
                hv[l4*4+0] += c * w.x; hv[l4*4+1] += c * w.y;
                hv[l4*4+2] += c * w.z; hv[l4*4+3] += c * w.w;
            }
        }
#pragma unroll
        for (int l = 0; l < 16; l++) sh[l][tid] = fmaxf(hv[l], 0.f);
    } else {
#pragma unroll
        for (int l = 0; l < 16; l++) sh[l][tid] = 0.f;
    }
    __syncwarp();

    int q = tid & 3;
    int ihalf = q & 1;
    int ohalf = q >> 1;
    int base = tid & ~3;

    float xv[4][16];   // h1[src][ihalf*16 .. +16]
#pragma unroll
    for (int j = 0; j < 4; j++) {
        int e = eBase + base + j;
        int src = (e < Ee) ? ei[e] : 0;
        const float4* p = (const float4*)(&g_h1[src * H1c + ihalf * 16]);
#pragma unroll
        for (int r = 0; r < 4; r++) {
            float4 v = p[r];
            xv[j][r*4+0]=v.x; xv[j][r*4+1]=v.y; xv[j][r*4+2]=v.z; xv[j][r*4+3]=v.w;
        }
    }

    u64 acc2[4][4];
#pragma unroll
    for (int j = 0; j < 4; j++)
#pragma unroll
        for (int p = 0; p < 4; p++) acc2[j][p] = 0ull;

    // bias term (this thread's i-half, o-half)
#pragma unroll
    for (int ii = 0; ii < 16; ii++) {
        int i = ihalf * 16 + ii;
        const ulonglong2* bw = (const ulonglong2*)&sbb4[i * 4 + ohalf * 2];
        ulonglong2 ua = bw[0], ub = bw[1];
#pragma unroll
        for (int j = 0; j < 4; j++) {
            u64 cc = pk2(xv[j][ii]);
            fma2(acc2[j][0], ua.x, cc); fma2(acc2[j][1], ua.y, cc);
            fma2(acc2[j][2], ub.x, cc); fma2(acc2[j][3], ub.y, cc);
        }
    }
    // main term: hk via one LDS.128
#pragma unroll 1
    for (int k = 0; k < 16; k++) {
        float4 hk4 = *(const float4*)&sh[k][base];
        float hk[4] = {hk4.x, hk4.y, hk4.z, hk4.w};
        const float4* wk = &sw4[k * 128 + ihalf * 64 + ohalf * 2];
#pragma unroll
        for (int ii = 0; ii < 16; ii++) {
            const ulonglong2* wp = (const ulonglong2*)&wk[ii * 4];
            ulonglong2 ua = wp[0], ub = wp[1];
#pragma unroll
            for (int j = 0; j < 4; j++) {
                u64 cc = pk2(hk[j] * xv[j][ii]);
                fma2(acc2[j][0], ua.x, cc); fma2(acc2[j][1], ua.y, cc);
                fma2(acc2[j][2], ub.x, cc); fma2(acc2[j][3], ub.y, cc);
            }
        }
    }
    // combine the two i-halves (partner = q^1, same o-half)
#pragma unroll
    for (int j = 0; j < 4; j++)
#pragma unroll
        for (int p = 0; p < 4; p++)
            acc2[j][p] = add2(acc2[j][p],
                              __shfl_xor_sync(0xffffffffu, acc2[j][p], 1));
    if (ihalf == 0) {
        // targets loaded AFTER the mainloop (keeps them out of loop liveness)
#pragma unroll
        for (int j = 0; j < 4; j++) {
            int e = eBase + base + j;
            if (e >= Ee) continue;
            int tgt = ei[Ee + e];
            float* dst = &g_agg2[tgt * H2c + ohalf * 8];
#pragma unroll
            for (int p = 0; p < 4; p++) {
                float lo, hi; upk(acc2[j][p], lo, hi);
                atomicAdd(dst + 2 * p + 0, lo);
                atomicAdd(dst + 2 * p + 1, hi);
            }
        }
    }
}

// ---------------- node2: 2 threads per node (o-half), warp-collapsed atomics --
__global__ void __launch_bounds__(256) k_node2(
        const float* __restrict__ wr, const float* __restrict__ br,
        const int* __restrict__ batch) {
    __shared__ float sw[H1c * H2c], sb[H2c];
    int tid = threadIdx.x;
    for (int t = tid; t < H1c * H2c; t += blockDim.x) sw[t] = wr[t];
    if (tid < H2c) sb[tid] = br[tid];
    __syncthreads();
    int gid = blockIdx.x * blockDim.x + tid;
    int n = gid >> 1, h = gid & 1;
    bool valid = n < Nn;
    int b = valid ? batch[n] : -1;
    float v[8];
#pragma unroll
    for (int o = 0; o < 8; o++) v[o] = 0.f;
    if (valid) {
        float hv[H1c];
        const float4* hp = (const float4*)(&g_h1[n * H1c]);
#pragma unroll
        for (int r = 0; r < 8; r++) {
            float4 t4 = hp[r];
            hv[r*4+0]=t4.x; hv[r*4+1]=t4.y; hv[r*4+2]=t4.z; hv[r*4+3]=t4.w;
        }
        const float4* ap = (const float4*)(&g_agg2[n * H2c + h * 8]);
        float4 a0 = ap[0], a1 = ap[1];
        float ag[8] = {a0.x,a0.y,a0.z,a0.w,a1.x,a1.y,a1.z,a1.w};
#pragma unroll
        for (int oo = 0; oo < 8; oo++) {
            int o = h * 8 + oo;
            float t = sb[o] + ag[oo];
#pragma unroll
            for (int i = 0; i < H1c; i++) t += hv[i] * sw[i * H2c + o];
            v[oo] = fmaxf(t, 0.f);
        }
    }
    const unsigned m = 0xffffffffu;
    int b0 = __shfl_sync(m, b, 0);
    if (__all_sync(m, valid && (b == b0))) {
        // parity-preserving reduce: sums the 16 nodes, keeps halves separate
#pragma unroll
        for (int d = 16; d >= 2; d >>= 1)
#pragma unroll
            for (int o = 0; o < 8; o++) v[o] += __shfl_xor_sync(m, v[o], d);
        if ((tid & 31) < 2) {
#pragma unroll
            for (int o = 0; o < 8; o++)
                atomicAdd(&g_h2sum[b0 * H2c + h * 8 + o], v[o]);
        }
    } else if (valid) {
#pragma unroll
        for (int o = 0; o < 8; o++)
            atomicAdd(&g_h2sum[b * H2c + h * 8 + o], v[o]);
    }
}

// ---------------- final head per graph ----------------------------------------
__global__ void k_final(float* __restrict__ out,
                        const float* __restrict__ wl1, const float* __restrict__ bl1,
                        const float* __restrict__ wl2, const float* __restrict__ bl2) {
    int g = blockIdx.x * blockDim.x + threadIdx.x;
    if (g >= Gg) return;
    float cnt = fmaxf(g_cnt[g], 1.f);
    float s = g_s[g];
    float invs = (s > 0.f) ? (1.f / s) : 0.f;
    float z[H2c + FN];
#pragma unroll
    for (int o = 0; o < H2c; o++) z[o] = g_h2sum[g * H2c + o] / cnt;
#pragma unroll
    for (int f = 0; f < FN; f++) z[H2c + f] = g_num[g * FN + f] * invs;
    float y[8];
#pragma unroll
    for (int j = 0; j < 8; j++) {
        float v = __ldg(&bl1[j]);
#pragma unroll
        for (int c = 0; c < H2c + FN; c++) v += z[c] * __ldg(&wl1[c * 8 + j]);
        y[j] = v;
    }
    float r = __ldg(&bl2[0]);
#pragma unroll
    for (int j = 0; j < 8; j++) r += y[j] * __ldg(&wl2[j]);
    out[g] = r;
}

// ---------------- launch ------------------------------------------------------
extern "C" void kernel_launch(void* const* d_in, const int* in_sizes, int n_in,
                              void* d_out, int out_size) {
    const float* x       = (const float*)d_in[0];
    const float* ea      = (const float*)d_in[1];
    const float* w_e1a   = (const float*)d_in[2];
    const float* b_e1a   = (const float*)d_in[3];
    const float* w_e1b   = (const float*)d_in[4];
    const float* b_e1b   = (const float*)d_in[5];
    const float* w_root1 = (const float*)d_in[6];
    const float* b_root1 = (const float*)d_in[7];
    const float* w_e2a   = (const float*)d_in[8];
    const float* b_e2a   = (const float*)d_in[9];
    const float* w_e2b   = (const float*)d_in[10];
    const float* b_e2b   = (const float*)d_in[11];
    const float* w_root2 = (const float*)d_in[12];
    const float* b_root2 = (const float*)d_in[13];
    const float* w_g1    = (const float*)d_in[14];
    const float* b_g1    = (const float*)d_in[15];
    const float* w_g2    = (const float*)d_in[16];
    const float* b_g2    = (const float*)d_in[17];
    const float* w_l1    = (const float*)d_in[18];
    const float* b_l1    = (const float*)d_in[19];
    const float* w_l2    = (const float*)d_in[20];
    const float* b_l2    = (const float*)d_in[21];
    const int*   ei      = (const int*)d_in[22];
    const int*   batch   = (const int*)d_in[23];
    float* out = (float*)d_out;

    int nblk  = (Nn + 255) / 256;
    int nblk2 = (2 * Nn + 255) / 256;
    k_gate<<<nblk, 256>>>(x, w_g1, b_g1, w_g2, b_g2);
    k_fused1<<<EBLK + ABLK, 128>>>(x, ea, w_e1a, b_e1a, w_e1b, b_e1b, ei, batch);
    k_node1<<<nblk2, 256>>>(x, w_root1, b_root1);
    k_conv2<<<EBLK, 128>>>(ea, w_e2a, b_e2a, w_e2b, b_e2b, ei);
    k_node2<<<nblk2, 256>>>(w_root2, b_root2, batch);
    k_final<<<(Gg + 255) / 256, 256>>>(out, w_l1, b_l1, w_l2, b_l2);
}

// round 16
// speedup vs baseline: 1.0099x; 1.0099x over previous
#include <cuda_runtime.h>

// Problem constants
#define Nn 100000
#define Ee 200000
#define Gg 2500
#define FN 16
#define FE 8
#define H1c 32
#define H2c 16
#define EBLK 1563   // ceil(Ee/128)
#define ABLK 782    // ceil(Nn/128)

typedef unsigned long long u64;

// ---- packed f32x2 helpers (sm_103a FFMA2 path) --------------------------------
__device__ __forceinline__ u64 pk2(float v) {
    u64 r; asm("mov.b64 %0, {%1, %1};" : "=l"(r) : "r"(__float_as_uint(v)));
    return r;
}
__device__ __forceinline__ void fma2(u64& d, u64 a, u64 b) {
    asm("fma.rn.f32x2 %0, %1, %2, %0;" : "+l"(d) : "l"(a), "l"(b));
}
__device__ __forceinline__ u64 add2(u64 a, u64 b) {
    u64 r; asm("add.rn.f32x2 %0, %1, %2;" : "=l"(r) : "l"(a), "l"(b));
    return r;
}
__device__ __forceinline__ void upk(u64 v, float& lo, float& hi) {
    unsigned a, b;
    asm("mov.b64 {%0, %1}, %2;" : "=r"(a), "=r"(b) : "l"(v));
    lo = __uint_as_float(a); hi = __uint_as_float(b);
}

// ---------------- scratch (device globals; no allocation allowed) -------------
__device__ float    g_gate[Nn];      // stores exp(gate) (no max-shift; gates O(0.3))
__device__ float    g_s[Gg];
__device__ float    g_num[Gg * FN];
__device__ float    g_cnt[Gg];
__device__ float    g_agg1[Nn * H1c];
__device__ float    g_h1[Nn * H1c];
__device__ float    g_agg2[Nn * H2c];
__device__ float    g_h2sum[Gg * H2c];

// ------ gate (stores exp) + zero node aggs + zero graph scratch (low gids) ----
__global__ void k_gate(const float* __restrict__ x,
                       const float* __restrict__ wg1, const float* __restrict__ bg1,
                       const float* __restrict__ wg2, const float* __restrict__ bg2) {
    __shared__ float sw1[FN * FN], sb1[FN], sw2[FN], sb2;
    int tid = threadIdx.x;
    if (tid < FN * FN) sw1[tid] = wg1[tid];
    if (tid < FN) { sb1[tid] = bg1[tid]; sw2[tid] = wg2[tid]; }
    if (tid == 0) sb2 = bg2[0];
    __syncthreads();
    int n = blockIdx.x * blockDim.x + tid;
    // zero per-graph scratch (consumed only by LATER kernels; boundary orders it)
    if (n < Gg) { g_s[n] = 0.f; g_cnt[n] = 0.f; }
    if (n < Gg * FN) g_num[n] = 0.f;
    if (n < Gg * H2c) g_h2sum[n] = 0.f;
    if (n >= Nn) return;
    // zero this node's aggregation rows
    float4 z4 = make_float4(0.f, 0.f, 0.f, 0.f);
    float4* a1 = (float4*)(&g_agg1[n * H1c]);
    float4* a2 = (float4*)(&g_agg2[n * H2c]);
#pragma unroll
    for (int r = 0; r < H1c / 4; r++) a1[r] = z4;
#pragma unroll
    for (int r = 0; r < H2c / 4; r++) a2[r] = z4;

    float xv[FN];
#pragma unroll
    for (int i = 0; i < FN; i++) xv[i] = x[n * FN + i];
    float g = sb2;
#pragma unroll
    for (int j = 0; j < FN; j++) {
        float h = sb1[j];
#pragma unroll
        for (int i = 0; i < FN; i++) h += xv[i] * sw1[i * FN + j];
        g += fmaxf(h, 0.f) * sw2[j];
    }
    g_gate[n] = expf(g);   // softmax is shift-invariant; no max-shift needed
}

// ---------------- fused: conv1 (blocks [0,EBLK)) + att (blocks [EBLK,..)) -----
__global__ void __launch_bounds__(128, 4) k_fused1(
        const float* __restrict__ x, const float* __restrict__ ea,
        const float* __restrict__ w_e1a, const float* __restrict__ b_e1a,
        const float* __restrict__ w_e1b, const float* __restrict__ b_e1b,
        const int* __restrict__ ei, const int* __restrict__ batch) {
    __shared__ float4 sw4[16 * 16 * 8];   // w_e1b [k][i][o4]
    __shared__ float4 sbb4[16 * 8];       // b_e1b [i][o4]
    __shared__ float4 swa4[FE * 4];
    __shared__ float  sba[16];
    __shared__ float  sh[16][128];        // h[k][edge-slot]
    int tid = threadIdx.x;

    if (blockIdx.x >= EBLK) {
        // ---------------- attention-softmax accumulation path ----------------
        int n = (blockIdx.x - EBLK) * 128 + tid;
        bool valid = n < Nn;
        int b = valid ? batch[n] : -1;
        float a = 0.f;
        float xs[FN];
#pragma unroll
        for (int f = 0; f < FN; f++) xs[f] = 0.f;
        if (valid) {
            a = g_gate[n];   // already exp(gate)
            const float4* xp = (const float4*)(x + n * FN);
#pragma unroll
            for (int r = 0; r < 4; r++) {
                float4 v = xp[r];
                xs[r*4+0]=v.x; xs[r*4+1]=v.y; xs[r*4+2]=v.z; xs[r*4+3]=v.w;
            }
        }
        const unsigned m = 0xffffffffu;
        int b0 = __shfl_sync(m, b, 0);
        if (__all_sync(m, valid && (b == b0))) {
            float sa = a;
            float v[FN];
#pragma unroll
            for (int f = 0; f < FN; f++) v[f] = a * xs[f];
#pragma unroll
            for (int d = 16; d; d >>= 1) {
                sa += __shfl_xor_sync(m, sa, d);
#pragma unroll
                for (int f = 0; f < FN; f++) v[f] += __shfl_xor_sync(m, v[f], d);
            }
            if ((tid & 31) == 0) {
                atomicAdd(&g_s[b0], sa);
                atomicAdd(&g_cnt[b0], 32.f);
#pragma unroll
                for (int f = 0; f < FN; f++) atomicAdd(&g_num[b0 * FN + f], v[f]);
            }
        } else if (valid) {
            atomicAdd(&g_s[b], a);
            atomicAdd(&g_cnt[b], 1.f);
#pragma unroll
            for (int f = 0; f < FN; f++)
                atomicAdd(&g_num[b * FN + f], a * xs[f]);
        }
        return;
    }

    // ---------------- conv1 path: 4 edges / 4-thread group, o-quarter --------
    for (int t = tid; t < 16 * 16 * 8; t += 128) sw4[t] = ((const float4*)w_e1b)[t];
    for (int t = tid; t < 16 * 8;      t += 128) sbb4[t] = ((const float4*)b_e1b)[t];
    if (tid < FE * 4) swa4[tid] = ((const float4*)w_e1a)[tid];
    if (tid < 16) sba[tid] = b_e1a[tid];
    __syncthreads();

    int eBase = blockIdx.x * 128;
    int myE = eBase + tid;
    if (myE < Ee) {
        const float4* eap = (const float4*)(ea + myE * FE);
        float4 a0 = eap[0], a1 = eap[1];
        float eav[FE] = {a0.x,a0.y,a0.z,a0.w,a1.x,a1.y,a1.z,a1.w};
        float hv[16];
#pragma unroll
        for (int l = 0; l < 16; l++) hv[l] = sba[l];
#pragma unroll
        for (int j = 0; j < FE; j++) {
            float c = eav[j];
#pragma unroll
            for (int l4 = 0; l4 < 4; l4++) {
                float4 w = swa4[j * 4 + l4];
                hv[l4*4+0] += c * w.x; hv[l4*4+1] += c * w.y;
                hv[l4*4+2] += c * w.z; hv[l4*4+3] += c * w.w;
            }
        }
#pragma unroll
        for (int l = 0; l < 16; l++) sh[l][tid] = fmaxf(hv[l], 0.f);
    } else {
#pragma unroll
        for (int l = 0; l < 16; l++) sh[l][tid] = 0.f;
    }
    __syncwarp();

    int q = tid & 3;          // o-quarter
    int base = tid & ~3;

    float xv[4][16];
#pragma unroll
    for (int j = 0; j < 4; j++) {
        int e = eBase + base + j;
        int src = (e < Ee) ? ei[e] : 0;
        const float4* p = (const float4*)(x + src * FN);
#pragma unroll
        for (int r = 0; r < 4; r++) {
            float4 v = p[r];
            xv[j][r*4+0]=v.x; xv[j][r*4+1]=v.y; xv[j][r*4+2]=v.z; xv[j][r*4+3]=v.w;
        }
    }

    u64 acc2[4][4];   // [edge][o-pair], packed (o, o+1)
#pragma unroll
    for (int j = 0; j < 4; j++)
#pragma unroll
        for (int p = 0; p < 4; p++) acc2[j][p] = 0ull;

    // bias term
#pragma unroll
    for (int i = 0; i < 16; i++) {
        const ulonglong2* bw = (const ulonglong2*)&sbb4[i * 8 + q * 2];
        ulonglong2 ua = bw[0], ub = bw[1];
#pragma unroll
        for (int j = 0; j < 4; j++) {
            u64 cc = pk2(xv[j][i]);
            fma2(acc2[j][0], ua.x, cc); fma2(acc2[j][1], ua.y, cc);
            fma2(acc2[j][2], ub.x, cc); fma2(acc2[j][3], ub.y, cc);
        }
    }
    // main term: hk via one LDS.128 (sh row is 16B-aligned at base)
#pragma unroll 1
    for (int k = 0; k < 16; k++) {
        float4 hk4 = *(const float4*)&sh[k][base];
        float hk[4] = {hk4.x, hk4.y, hk4.z, hk4.w};
        const float4* wk = &sw4[k * 128 + q * 2];
#pragma unroll
        for (int i = 0; i < 16; i++) {
            const ulonglong2* wp = (const ulonglong2*)&wk[i * 8];
            ulonglong2 ua = wp[0], ub = wp[1];
#pragma unroll
            for (int j = 0; j < 4; j++) {
                u64 cc = pk2(hk[j] * xv[j][i]);
                fma2(acc2[j][0], ua.x, cc); fma2(acc2[j][1], ua.y, cc);
                fma2(acc2[j][2], ub.x, cc); fma2(acc2[j][3], ub.y, cc);
            }
        }
    }
    // targets loaded AFTER the mainloop
#pragma unroll
    for (int j = 0; j < 4; j++) {
        int e = eBase + base + j;
        if (e >= Ee) continue;
        int tgt = ei[Ee + e];
        float* dst = &g_agg1[tgt * H1c + q * 8];
#pragma unroll
        for (int p = 0; p < 4; p++) {
            float lo, hi; upk(acc2[j][p], lo, hi);
            atomicAdd(dst + 2 * p + 0, lo);
            atomicAdd(dst + 2 * p + 1, hi);
        }
    }
}

// ---------------- node1: 2 threads per node (o-half) --------------------------
__global__ void __launch_bounds__(256) k_node1(
        const float* __restrict__ x,
        const float* __restrict__ wr, const float* __restrict__ br) {
    __shared__ float sw[FN * H1c], sb[H1c];
    int tid = threadIdx.x;
    for (int t = tid; t < FN * H1c; t += blockDim.x) sw[t] = wr[t];
    if (tid < H1c) sb[tid] = br[tid];
    __syncthreads();
    int gid = blockIdx.x * blockDim.x + tid;
    int n = gid >> 1, h = gid & 1;
    if (n >= Nn) return;
    float xv[FN];
    {
        const float4* xp = (const float4*)(x + n * FN);
#pragma unroll
        for (int r = 0; r < 4; r++) {
            float4 v = xp[r];
            xv[r*4+0]=v.x; xv[r*4+1]=v.y; xv[r*4+2]=v.z; xv[r*4+3]=v.w;
        }
    }
    float acc[16];
    {
        const float4* ap = (const float4*)(&g_agg1[n * H1c + h * 16]);
#pragma unroll
        for (int r = 0; r < 4; r++) {
            float4 v = ap[r];
            acc[r*4+0]=v.x; acc[r*4+1]=v.y; acc[r*4+2]=v.z; acc[r*4+3]=v.w;
        }
    }
#pragma unroll
    for (int o = 0; o < 16; o++) {
        float v = acc[o] + sb[h * 16 + o];
#pragma unroll
        for (int i = 0; i < FN; i++) v += xv[i] * sw[i * H1c + h * 16 + o];
        acc[o] = fmaxf(v, 0.f);
    }
    float4* hp = (float4*)(&g_h1[n * H1c + h * 16]);
#pragma unroll
    for (int r = 0; r < 4; r++)
        hp[r] = make_float4(acc[r*4+0], acc[r*4+1], acc[r*4+2], acc[r*4+3]);
}

// ---------------- conv2: 4 edges / 4-thread group, (i-half x o-half), FFMA2 ---
__global__ void __launch_bounds__(128, 4) k_conv2(
        const float* __restrict__ ea,
        const float* __restrict__ w_e2a, const float* __restrict__ b_e2a,
        const float* __restrict__ w_e2b, const float* __restrict__ b_e2b,
        const int* __restrict__ ei) {
    __shared__ float4 sw4[16 * 32 * 4];   // w_e2b [k][i][o4]
    __shared__ float4 sbb4[32 * 4];       // b_e2b [i][o4]
    __shared__ float4 swa4[FE * 4];
    __shared__ float  sba[16];
    __shared__ float  sh[16][128];
    int tid = threadIdx.x;
    for (int t = tid; t < 16 * 32 * 4; t += 128) sw4[t] = ((const float4*)w_e2b)[t];
    for (int t = tid; t < 32 * 4;      t += 128) sbb4[t] = ((const float4*)b_e2b)[t];
    if (tid < FE * 4) swa4[tid] = ((const float4*)w_e2a)[tid];
    if (tid < 16) sba[tid] = b_e2a[tid];
    __syncthreads();

    int eBase = blockIdx.x * 128;
    int myE = eBase + tid;
    if (myE < Ee) {
        const float4* eap = (const float4*)(ea + myE * FE);
        float4 a0 = eap[0], a1 = eap[1];
        float eav[FE] = {a0.x,a0.y,a0.z,a0.w,a1.x,a1.y,a1.z,a1.w};
        float hv[16];
#pragma unroll
        for (int l = 0; l < 16; l++) hv[l] = sba[l];
#pragma unroll
        for (int j = 0; j < FE; j++) {
            float c = eav[j];
#pragma unroll
            for (int l4 = 0; l4 < 4; l4++) {
                float4 w = swa4[j * 4 + l4];
                hv[l4*4+0] += c * w.x; hv[l4*4+1] += c * w.y;
                hv[l4*4+2] += c * w.z; hv[l4*4+3] += c * w.w;
            }
        }
#pragma unroll
        for (int l = 0; l < 16; l++) sh[l][tid] = fmaxf(hv[l], 0.f);
    } else {
#pragma unroll
        for (int l = 0; l < 16; l++) sh[l][tid] = 0.f;
    }
    __syncwarp();

    int q = tid & 3;
    int ihalf = q & 1;
    int ohalf = q >> 1;
    int base = tid & ~3;

    float xv[4][16];   // h1[src][ihalf*16 .. +16]
#pragma unroll
    for (int j = 0; j < 4; j++) {
        int e = eBase + base + j;
        int src = (e < Ee) ? ei[e] : 0;
        const float4* p = (const float4*)(&g_h1[src * H1c + ihalf * 16]);
#pragma unroll
        for (int r = 0; r < 4; r++) {
            float4 v = p[r];
            xv[j][r*4+0]=v.x; xv[j][r*4+1]=v.y; xv[j][r*4+2]=v.z; xv[j][r*4+3]=v.w;
        }
    }

    u64 acc2[4][4];
#pragma unroll
    for (int j = 0; j < 4; j++)
#pragma unroll
        for (int p = 0; p < 4; p++) acc2[j][p] = 0ull;

    // bias term (this thread's i-half, o-half)
#pragma unroll
    for (int ii = 0; ii < 16; ii++) {
        int i = ihalf * 16 + ii;
        const ulonglong2* bw = (const ulonglong2*)&sbb4[i * 4 + ohalf * 2];
        ulonglong2 ua = bw[0], ub = bw[1];
#pragma unroll
        for (int j = 0; j < 4; j++) {
            u64 cc = pk2(xv[j][ii]);
            fma2(acc2[j][0], ua.x, cc); fma2(acc2[j][1], ua.y, cc);
            fma2(acc2[j][2], ub.x, cc); fma2(acc2[j][3], ub.y, cc);
        }
    }
    // main term: hk via one LDS.128
#pragma unroll 1
    for (int k = 0; k < 16; k++) {
        float4 hk4 = *(const float4*)&sh[k][base];
        float hk[4] = {hk4.x, hk4.y, hk4.z, hk4.w};
        const float4* wk = &sw4[k * 128 + ihalf * 64 + ohalf * 2];
#pragma unroll
        for (int ii = 0; ii < 16; ii++) {
            const ulonglong2* wp = (const ulonglong2*)&wk[ii * 4];
            ulonglong2 ua = wp[0], ub = wp[1];
#pragma unroll
            for (int j = 0; j < 4; j++) {
                u64 cc = pk2(hk[j] * xv[j][ii]);
                fma2(acc2[j][0], ua.x, cc); fma2(acc2[j][1], ua.y, cc);
                fma2(acc2[j][2], ub.x, cc); fma2(acc2[j][3], ub.y, cc);
            }
        }
    }
    // combine the two i-halves (partner = q^1, same o-half)
#pragma unroll
    for (int j = 0; j < 4; j++)
#pragma unroll
        for (int p = 0; p < 4; p++)
            acc2[j][p] = add2(acc2[j][p],
                              __shfl_xor_sync(0xffffffffu, acc2[j][p], 1));
    if (ihalf == 0) {
        // targets loaded AFTER the mainloop
#pragma unroll
        for (int j = 0; j < 4; j++) {
            int e = eBase + base + j;
            if (e >= Ee) continue;
            int tgt = ei[Ee + e];
            float* dst = &g_agg2[tgt * H2c + ohalf * 8];
#pragma unroll
            for (int p = 0; p < 4; p++) {
                float lo, hi; upk(acc2[j][p], lo, hi);
                atomicAdd(dst + 2 * p + 0, lo);
                atomicAdd(dst + 2 * p + 1, hi);
            }
        }
    }
}

// ---------------- node2: 2 threads per node (o-half), warp-collapsed atomics --
__global__ void __launch_bounds__(256) k_node2(
        const float* __restrict__ wr, const float* __restrict__ br,
        const int* __restrict__ batch) {
    __shared__ float sw[H1c * H2c], sb[H2c];
    int tid = threadIdx.x;
    for (int t = tid; t < H1c * H2c; t += blockDim.x) sw[t] = wr[t];
    if (tid < H2c) sb[tid] = br[tid];
    __syncthreads();
    int gid = blockIdx.x * blockDim.x + tid;
    int n = gid >> 1, h = gid & 1;
    bool valid = n < Nn;
    int b = valid ? batch[n] : -1;
    float v[8];
#pragma unroll
    for (int o = 0; o < 8; o++) v[o] = 0.f;
    if (valid) {
        float hv[H1c];
        const float4* hp = (const float4*)(&g_h1[n * H1c]);
#pragma unroll
        for (int r = 0; r < 8; r++) {
            float4 t4 = hp[r];
            hv[r*4+0]=t4.x; hv[r*4+1]=t4.y; hv[r*4+2]=t4.z; hv[r*4+3]=t4.w;
        }
        const float4* ap = (const float4*)(&g_agg2[n * H2c + h * 8]);
        float4 a0 = ap[0], a1 = ap[1];
        float ag[8] = {a0.x,a0.y,a0.z,a0.w,a1.x,a1.y,a1.z,a1.w};
#pragma unroll
        for (int oo = 0; oo < 8; oo++) {
            int o = h * 8 + oo;
            float t = sb[o] + ag[oo];
#pragma unroll
            for (int i = 0; i < H1c; i++) t += hv[i] * sw[i * H2c + o];
            v[oo] = fmaxf(t, 0.f);
        }
    }
    const unsigned m = 0xffffffffu;
    int b0 = __shfl_sync(m, b, 0);
    if (__all_sync(m, valid && (b == b0))) {
        // parity-preserving reduce: sums the 16 nodes, keeps halves separate
#pragma unroll
        for (int d = 16; d >= 2; d >>= 1)
#pragma unroll
            for (int o = 0; o < 8; o++) v[o] += __shfl_xor_sync(m, v[o], d);
        if ((tid & 31) < 2) {
#pragma unroll
            for (int o = 0; o < 8; o++)
                atomicAdd(&g_h2sum[b0 * H2c + h * 8 + o], v[o]);
        }
    } else if (valid) {
#pragma unroll
        for (int o = 0; o < 8; o++)
            atomicAdd(&g_h2sum[b * H2c + h * 8 + o], v[o]);
    }
}

// ---------------- final head per graph ----------------------------------------
__global__ void k_final(float* __restrict__ out,
                        const float* __restrict__ wl1, const float* __restrict__ bl1,
                        const float* __restrict__ wl2, const float* __restrict__ bl2) {
    int g = blockIdx.x * blockDim.x + threadIdx.x;
    if (g >= Gg) return;
    float cnt = fmaxf(g_cnt[g], 1.f);
    float s = g_s[g];
    float invs = (s > 0.f) ? (1.f / s) : 0.f;
    float z[H2c + FN];
#pragma unroll
    for (int o = 0; o < H2c; o++) z[o] = g_h2sum[g * H2c + o] / cnt;
#pragma unroll
    for (int f = 0; f < FN; f++) z[H2c + f] = g_num[g * FN + f] * invs;
    float y[8];
#pragma unroll
    for (int j = 0; j < 8; j++) {
        float v = __ldg(&bl1[j]);
#pragma unroll
        for (int c = 0; c < H2c + FN; c++) v += z[c] * __ldg(&wl1[c * 8 + j]);
        y[j] = v;
    }
    float r = __ldg(&bl2[0]);
#pragma unroll
    for (int j = 0; j < 8; j++) r += y[j] * __ldg(&wl2[j]);
    out[g] = r;
}

// ---------------- launch ------------------------------------------------------
extern "C" void kernel_launch(void* const* d_in, const int* in_sizes, int n_in,
                              void* d_out, int out_size) {
    const float* x       = (const float*)d_in[0];
    const float* ea      = (const float*)d_in[1];
    const float* w_e1a   = (const float*)d_in[2];
    const float* b_e1a   = (const float*)d_in[3];
    const float* w_e1b   = (const float*)d_in[4];
    const float* b_e1b   = (const float*)d_in[5];
    const float* w_root1 = (const float*)d_in[6];
    const float* b_root1 = (const float*)d_in[7];
    const float* w_e2a   = (const float*)d_in[8];
    const float* b_e2a   = (const float*)d_in[9];
    const float* w_e2b   = (const float*)d_in[10];
    const float* b_e2b   = (const float*)d_in[11];
    const float* w_root2 = (const float*)d_in[12];
    const float* b_root2 = (const float*)d_in[13];
    const float* w_g1    = (const float*)d_in[14];
    const float* b_g1    = (const float*)d_in[15];
    const float* w_g2    = (const float*)d_in[16];
    const float* b_g2    = (const float*)d_in[17];
    const float* w_l1    = (const float*)d_in[18];
    const float* b_l1    = (const float*)d_in[19];
    const float* w_l2    = (const float*)d_in[20];
    const float* b_l2    = (const float*)d_in[21];
    const int*   ei      = (const int*)d_in[22];
    const int*   batch   = (const int*)d_in[23];
    float* out = (float*)d_out;

    int nblk  = (Nn + 255) / 256;
    int nblk2 = (2 * Nn + 255) / 256;
    k_gate<<<nblk, 256>>>(x, w_g1, b_g1, w_g2, b_g2);
    k_fused1<<<EBLK + ABLK, 128>>>(x, ea, w_e1a, b_e1a, w_e1b, b_e1b, ei, batch);
    k_node1<<<nblk2, 256>>>(x, w_root1, b_root1);
    k_conv2<<<EBLK, 128>>>(ea, w_e2a, b_e2a, w_e2b, b_e2b, ei);
    k_node2<<<nblk2, 256>>>(w_root2, b_root2, batch);
    k_final<<<(Gg + 255) / 256, 256>>>(out, w_l1, b_l1, w_l2, b_l2);
}

// round 17
// speedup vs baseline: 1.2415x; 1.2293x over previous
#include <cuda_runtime.h>

// Problem constants
#define Nn 100000
#define Ee 200000
#define Gg 2500
#define FN 16
#define FE 8
#define H1c 32
#define H2c 16
#define EBLK 1563   // ceil(Ee/128)
#define ABLK 782    // ceil(Nn/128)

typedef unsigned long long u64;

// ---- packed f32x2 helpers (sm_103a FFMA2 path) --------------------------------
__device__ __forceinline__ u64 pk2(float v) {
    u64 r; asm("mov.b64 %0, {%1, %1};" : "=l"(r) : "r"(__float_as_uint(v)));
    return r;
}
__device__ __forceinline__ void fma2(u64& d, u64 a, u64 b) {
    asm("fma.rn.f32x2 %0, %1, %2, %0;" : "+l"(d) : "l"(a), "l"(b));
}
__device__ __forceinline__ u64 add2(u64 a, u64 b) {
    u64 r; asm("add.rn.f32x2 %0, %1, %2;" : "=l"(r) : "l"(a), "l"(b));
    return r;
}
__device__ __forceinline__ void upk(u64 v, float& lo, float& hi) {
    unsigned a, b;
    asm("mov.b64 {%0, %1}, %2;" : "=r"(a), "=r"(b) : "l"(v));
    lo = __uint_as_float(a); hi = __uint_as_float(b);
}

// ---------------- scratch (device globals; no allocation allowed) -------------
__device__ float    g_gate[Nn];      // stores exp(gate) (no max-shift; gates O(0.3))
__device__ float    g_s[Gg];
__device__ float    g_num[Gg * FN];
__device__ float    g_cnt[Gg];
__device__ float    g_agg1[Nn * H1c];
__device__ float    g_h1[Nn * H1c];
__device__ float    g_agg2[Nn * H2c];
__device__ float    g_h2sum[Gg * H2c];

// ------ gate (stores exp) + zero node aggs + zero graph scratch (low gids) ----
__global__ void k_gate(const float* __restrict__ x,
                       const float* __restrict__ wg1, const float* __restrict__ bg1,
                       const float* __restrict__ wg2, const float* __restrict__ bg2) {
    __shared__ float sw1[FN * FN], sb1[FN], sw2[FN], sb2;
    int tid = threadIdx.x;
    if (tid < FN * FN) sw1[tid] = wg1[tid];
    if (tid < FN) { sb1[tid] = bg1[tid]; sw2[tid] = wg2[tid]; }
    if (tid == 0) sb2 = bg2[0];
    __syncthreads();
    int n = blockIdx.x * blockDim.x + tid;
    // zero per-graph scratch (consumed only by LATER kernels; boundary orders it)
    if (n < Gg) { g_s[n] = 0.f; g_cnt[n] = 0.f; }
    if (n < Gg * FN) g_num[n] = 0.f;
    if (n < Gg * H2c) g_h2sum[n] = 0.f;
    if (n >= Nn) return;
    // zero this node's aggregation rows
    float4 z4 = make_float4(0.f, 0.f, 0.f, 0.f);
    float4* a1 = (float4*)(&g_agg1[n * H1c]);
    float4* a2 = (float4*)(&g_agg2[n * H2c]);
#pragma unroll
    for (int r = 0; r < H1c / 4; r++) a1[r] = z4;
#pragma unroll
    for (int r = 0; r < H2c / 4; r++) a2[r] = z4;

    float xv[FN];
#pragma unroll
    for (int i = 0; i < FN; i++) xv[i] = x[n * FN + i];
    float g = sb2;
#pragma unroll
    for (int j = 0; j < FN; j++) {
        float h = sb1[j];
#pragma unroll
        for (int i = 0; i < FN; i++) h += xv[i] * sw1[i * FN + j];
        g += fmaxf(h, 0.f) * sw2[j];
    }
    g_gate[n] = expf(g);   // softmax is shift-invariant; no max-shift needed
}

// ---------------- fused: conv1 (blocks [0,EBLK)) + att (blocks [EBLK,..)) -----
__global__ void __launch_bounds__(128, 4) k_fused1(
        const float* __restrict__ x, const float* __restrict__ ea,
        const float* __restrict__ w_e1a, const float* __restrict__ b_e1a,
        const float* __restrict__ w_e1b, const float* __restrict__ b_e1b,
        const int* __restrict__ ei, const int* __restrict__ batch) {
    __shared__ float4 sw4[16 * 16 * 8];   // w_e1b [k][i][o4]
    __shared__ float4 sbb4[16 * 8];       // b_e1b [i][o4]
    __shared__ float4 swa4[FE * 4];
    __shared__ float  sba[16];
    __shared__ float  sh[16][128];        // h[k][edge-slot]
    int tid = threadIdx.x;

    if (blockIdx.x >= EBLK) {
        // ---------------- attention-softmax accumulation path ----------------
        int n = (blockIdx.x - EBLK) * 128 + tid;
        bool valid = n < Nn;
        int b = valid ? batch[n] : -1;
        float a = 0.f;
        float xs[FN];
#pragma unroll
        for (int f = 0; f < FN; f++) xs[f] = 0.f;
        if (valid) {
            a = g_gate[n];   // already exp(gate)
            const float4* xp = (const float4*)(x + n * FN);
#pragma unroll
            for (int r = 0; r < 4; r++) {
                float4 v = xp[r];
                xs[r*4+0]=v.x; xs[r*4+1]=v.y; xs[r*4+2]=v.z; xs[r*4+3]=v.w;
            }
        }
        const unsigned m = 0xffffffffu;
        int b0 = __shfl_sync(m, b, 0);
        if (__all_sync(m, valid && (b == b0))) {
            float sa = a;
            float v[FN];
#pragma unroll
            for (int f = 0; f < FN; f++) v[f] = a * xs[f];
#pragma unroll
            for (int d = 16; d; d >>= 1) {
                sa += __shfl_xor_sync(m, sa, d);
#pragma unroll
                for (int f = 0; f < FN; f++) v[f] += __shfl_xor_sync(m, v[f], d);
            }
            if ((tid & 31) == 0) {
                atomicAdd(&g_s[b0], sa);
                atomicAdd(&g_cnt[b0], 32.f);
#pragma unroll
                for (int f = 0; f < FN; f++) atomicAdd(&g_num[b0 * FN + f], v[f]);
            }
        } else if (valid) {
            atomicAdd(&g_s[b], a);
            atomicAdd(&g_cnt[b], 1.f);
#pragma unroll
            for (int f = 0; f < FN; f++)
                atomicAdd(&g_num[b * FN + f], a * xs[f]);
        }
        return;
    }

    // ---------------- conv1 path: 4 edges / 4-thread group, o-quarter --------
    for (int t = tid; t < 16 * 16 * 8; t += 128) sw4[t] = ((const float4*)w_e1b)[t];
    for (int t = tid; t < 16 * 8;      t += 128) sbb4[t] = ((const float4*)b_e1b)[t];
    if (tid < FE * 4) swa4[tid] = ((const float4*)w_e1a)[tid];
    if (tid < 16) sba[tid] = b_e1a[tid];
    __syncthreads();

    int eBase = blockIdx.x * 128;
    int myE = eBase + tid;
    if (myE < Ee) {
        const float4* eap = (const float4*)(ea + myE * FE);
        float4 a0 = eap[0], a1 = eap[1];
        float eav[FE] = {a0.x,a0.y,a0.z,a0.w,a1.x,a1.y,a1.z,a1.w};
        float hv[16];
#pragma unroll
        for (int l = 0; l < 16; l++) hv[l] = sba[l];
#pragma unroll
        for (int j = 0; j < FE; j++) {
            float c = eav[j];
#pragma unroll
            for (int l4 = 0; l4 < 4; l4++) {
                float4 w = swa4[j * 4 + l4];
                hv[l4*4+0] += c * w.x; hv[l4*4+1] += c * w.y;
                hv[l4*4+2] += c * w.z; hv[l4*4+3] += c * w.w;
            }
        }
#pragma unroll
        for (int l = 0; l < 16; l++) sh[l][tid] = fmaxf(hv[l], 0.f);
    } else {
#pragma unroll
        for (int l = 0; l < 16; l++) sh[l][tid] = 0.f;
    }
    __syncwarp();

    int q = tid & 3;          // o-quarter
    int base = tid & ~3;

    float xv[4][16];
#pragma unroll
    for (int j = 0; j < 4; j++) {
        int e = eBase + base + j;
        int src = (e < Ee) ? ei[e] : 0;
        const float4* p = (const float4*)(x + src * FN);
#pragma unroll
        for (int r = 0; r < 4; r++) {
            float4 v = p[r];
            xv[j][r*4+0]=v.x; xv[j][r*4+1]=v.y; xv[j][r*4+2]=v.z; xv[j][r*4+3]=v.w;
        }
    }

    u64 acc2[4][4];   // [edge][o-pair], packed (o, o+1)
#pragma unroll
    for (int j = 0; j < 4; j++)
#pragma unroll
        for (int p = 0; p < 4; p++) acc2[j][p] = 0ull;

    // bias term
#pragma unroll
    for (int i = 0; i < 16; i++) {
        const ulonglong2* bw = (const ulonglong2*)&sbb4[i * 8 + q * 2];
        ulonglong2 ua = bw[0], ub = bw[1];
#pragma unroll
        for (int j = 0; j < 4; j++) {
            u64 cc = pk2(xv[j][i]);
            fma2(acc2[j][0], ua.x, cc); fma2(acc2[j][1], ua.y, cc);
            fma2(acc2[j][2], ub.x, cc); fma2(acc2[j][3], ub.y, cc);
        }
    }
    // main term: hk via one LDS.128 (sh row is 16B-aligned at base)
#pragma unroll 1
    for (int k = 0; k < 16; k++) {
        float4 hk4 = *(const float4*)&sh[k][base];
        float hk[4] = {hk4.x, hk4.y, hk4.z, hk4.w};
        const float4* wk = &sw4[k * 128 + q * 2];
#pragma unroll
        for (int i = 0; i < 16; i++) {
            const ulonglong2* wp = (const ulonglong2*)&wk[i * 8];
            ulonglong2 ua = wp[0], ub = wp[1];
#pragma unroll
            for (int j = 0; j < 4; j++) {
                u64 cc = pk2(hk[j] * xv[j][i]);
                fma2(acc2[j][0], ua.x, cc); fma2(acc2[j][1], ua.y, cc);
                fma2(acc2[j][2], ub.x, cc); fma2(acc2[j][3], ub.y, cc);
            }
        }
    }
    // targets loaded AFTER the mainloop
#pragma unroll
    for (int j = 0; j < 4; j++) {
        int e = eBase + base + j;
        if (e >= Ee) continue;
        int tgt = ei[Ee + e];
        float* dst = &g_agg1[tgt * H1c + q * 8];
#pragma unroll
        for (int p = 0; p < 4; p++) {
            float lo, hi; upk(acc2[j][p], lo, hi);
            atomicAdd(dst + 2 * p + 0, lo);
            atomicAdd(dst + 2 * p + 1, hi);
        }
    }
}

// ---------------- node1: 2 threads per node (o-half) --------------------------
__global__ void __launch_bounds__(256) k_node1(
        const float* __restrict__ x,
        const float* __restrict__ wr, const float* __restrict__ br) {
    __shared__ float sw[FN * H1c], sb[H1c];
    int tid = threadIdx.x;
    for (int t = tid; t < FN * H1c; t += blockDim.x) sw[t] = wr[t];
    if (tid < H1c) sb[tid] = br[tid];
    __syncthreads();
    int gid = blockIdx.x * blockDim.x + tid;
    int n = gid >> 1, h = gid & 1;
    if (n >= Nn) return;
    float xv[FN];
    {
        const float4* xp = (const float4*)(x + n * FN);
#pragma unroll
        for (int r = 0; r < 4; r++) {
            float4 v = xp[r];
            xv[r*4+0]=v.x; xv[r*4+1]=v.y; xv[r*4+2]=v.z; xv[r*4+3]=v.w;
        }
    }
    float acc[16];
    {
        const float4* ap = (const float4*)(&g_agg1[n * H1c + h * 16]);
#pragma unroll
        for (int r = 0; r < 4; r++) {
            float4 v = ap[r];
            acc[r*4+0]=v.x; acc[r*4+1]=v.y; acc[r*4+2]=v.z; acc[r*4+3]=v.w;
        }
    }
#pragma unroll
    for (int o = 0; o < 16; o++) {
        float v = acc[o] + sb[h * 16 + o];
#pragma unroll
        for (int i = 0; i < FN; i++) v += xv[i] * sw[i * H1c + h * 16 + o];
        acc[o] = fmaxf(v, 0.f);
    }
    float4* hp = (float4*)(&g_h1[n * H1c + h * 16]);
#pragma unroll
    for (int r = 0; r < 4; r++)
        hp[r] = make_float4(acc[r*4+0], acc[r*4+1], acc[r*4+2], acc[r*4+3]);
}

// ---------------- conv2: 4 edges / group, (i-half x o-half), FFMA2 ------------
// Smem weight layout PERMUTED to kill bank conflicts:
//   src  [k][i][o4]          (i = ihalf*16+ii, o4 = ohalf*2+oq)
//   dst  k*128 + ii*8 + ihalf*4 + o4
// -> per-lane read offset becomes ihalf*4 + ohalf*2 in {0,2,4,6} (bytes 0/32/64/96)
__global__ void __launch_bounds__(128, 4) k_conv2(
        const float* __restrict__ ea,
        const float* __restrict__ w_e2a, const float* __restrict__ b_e2a,
        const float* __restrict__ w_e2b, const float* __restrict__ b_e2b,
        const int* __restrict__ ei) {
    __shared__ float4 sw4[16 * 32 * 4];   // permuted weights
    __shared__ float4 sbb4[32 * 4];       // permuted bias
    __shared__ float4 swa4[FE * 4];
    __shared__ float  sba[16];
    __shared__ float  sh[16][128];
    int tid = threadIdx.x;
    for (int t = tid; t < 16 * 32 * 4; t += 128) {
        int k = t >> 7, rem = t & 127;
        int i = rem >> 2, o4 = rem & 3;
        int ii = i & 15, ihalf = i >> 4;
        sw4[(k << 7) + (ii << 3) + (ihalf << 2) + o4] = ((const float4*)w_e2b)[t];
    }
    for (int t = tid; t < 32 * 4; t += 128) {
        int i = t >> 2, o4 = t & 3;
        int ii = i & 15, ihalf = i >> 4;
        sbb4[(ii << 3) + (ihalf << 2) + o4] = ((const float4*)b_e2b)[t];
    }
    if (tid < FE * 4) swa4[tid] = ((const float4*)w_e2a)[tid];
    if (tid < 16) sba[tid] = b_e2a[tid];
    __syncthreads();

    int eBase = blockIdx.x * 128;
    int myE = eBase + tid;
    if (myE < Ee) {
        const float4* eap = (const float4*)(ea + myE * FE);
        float4 a0 = eap[0], a1 = eap[1];
        float eav[FE] = {a0.x,a0.y,a0.z,a0.w,a1.x,a1.y,a1.z,a1.w};
        float hv[16];
#pragma unroll
        for (int l = 0; l < 16; l++) hv[l] = sba[l];
#pragma unroll
        for (int j = 0; j < FE; j++) {
            float c = eav[j];
#pragma unroll
            for (int l4 = 0; l4 < 4; l4++) {
                float4 w = swa4[j * 4 + l4];
                hv[l4*4+0] += c * w.x; hv[l4*4+1] += c * w.y;
                hv[l4*4+2] += c * w.z; hv[l4*4+3] += c * w.w;
            }
        }
#pragma unroll
        for (int l = 0; l < 16; l++) sh[l][tid] = fmaxf(hv[l], 0.f);
    } else {
#pragma unroll
        for (int l = 0; l < 16; l++) sh[l][tid] = 0.f;
    }
    __syncwarp();

    int q = tid & 3;
    int ihalf = q & 1;
    int ohalf = q >> 1;
    int base = tid & ~3;

    float xv[4][16];   // h1[src][ihalf*16 .. +16]
#pragma unroll
    for (int j = 0; j < 4; j++) {
        int e = eBase + base + j;
        int src = (e < Ee) ? ei[e] : 0;
        const float4* p = (const float4*)(&g_h1[src * H1c + ihalf * 16]);
#pragma unroll
        for (int r = 0; r < 4; r++) {
            float4 v = p[r];
            xv[j][r*4+0]=v.x; xv[j][r*4+1]=v.y; xv[j][r*4+2]=v.z; xv[j][r*4+3]=v.w;
        }
    }

    u64 acc2[4][4];
#pragma unroll
    for (int j = 0; j < 4; j++)
#pragma unroll
        for (int p = 0; p < 4; p++) acc2[j][p] = 0ull;

    int lofs = (ihalf << 2) + (ohalf << 1);   // {0,2,4,6}: conflict-free

    // bias term (permuted layout)
#pragma unroll
    for (int ii = 0; ii < 16; ii++) {
        const ulonglong2* bw = (const ulonglong2*)&sbb4[(ii << 3) + lofs];
        ulonglong2 ua = bw[0], ub = bw[1];
#pragma unroll
        for (int j = 0; j < 4; j++) {
            u64 cc = pk2(xv[j][ii]);
            fma2(acc2[j][0], ua.x, cc); fma2(acc2[j][1], ua.y, cc);
            fma2(acc2[j][2], ub.x, cc); fma2(acc2[j][3], ub.y, cc);
        }
    }
    // main term (permuted layout): hk via one LDS.128
#pragma unroll 1
    for (int k = 0; k < 16; k++) {
        float4 hk4 = *(const float4*)&sh[k][base];
        float hk[4] = {hk4.x, hk4.y, hk4.z, hk4.w};
        const float4* wk = &sw4[(k << 7) + lofs];
#pragma unroll
        for (int ii = 0; ii < 16; ii++) {
            const ulonglong2* wp = (const ulonglong2*)&wk[ii << 3];
            ulonglong2 ua = wp[0], ub = wp[1];
#pragma unroll
            for (int j = 0; j < 4; j++) {
                u64 cc = pk2(hk[j] * xv[j][ii]);
                fma2(acc2[j][0], ua.x, cc); fma2(acc2[j][1], ua.y, cc);
                fma2(acc2[j][2], ub.x, cc); fma2(acc2[j][3], ub.y, cc);
            }
        }
    }
    // combine the two i-halves (partner = q^1, same o-half)
#pragma unroll
    for (int j = 0; j < 4; j++)
#pragma unroll
        for (int p = 0; p < 4; p++)
            acc2[j][p] = add2(acc2[j][p],
                              __shfl_xor_sync(0xffffffffu, acc2[j][p], 1));
    if (ihalf == 0) {
        // targets loaded AFTER the mainloop
#pragma unroll
        for (int j = 0; j < 4; j++) {
            int e = eBase + base + j;
            if (e >= Ee) continue;
            int tgt = ei[Ee + e];
            float* dst = &g_agg2[tgt * H2c + ohalf * 8];
#pragma unroll
            for (int p = 0; p < 4; p++) {
                float lo, hi; upk(acc2[j][p], lo, hi);
                atomicAdd(dst + 2 * p + 0, lo);
                atomicAdd(dst + 2 * p + 1, hi);
            }
        }
    }
}

// ---------------- node2: 2 threads per node (o-half), warp-collapsed atomics --
__global__ void __launch_bounds__(256) k_node2(
        const float* __restrict__ wr, const float* __restrict__ br,
        const int* __restrict__ batch) {
    __shared__ float sw[H1c * H2c], sb[H2c];
    int tid = threadIdx.x;
    for (int t = tid; t < H1c * H2c; t += blockDim.x) sw[t] = wr[t];
    if (tid < H2c) sb[tid] = br[tid];
    __syncthreads();
    int gid = blockIdx.x * blockDim.x + tid;
    int n = gid >> 1, h = gid & 1;
    bool valid = n < Nn;
    int b = valid ? batch[n] : -1;
    float v[8];
#pragma unroll
    for (int o = 0; o < 8; o++) v[o] = 0.f;
    if (valid) {
        float hv[H1c];
        const float4* hp = (const float4*)(&g_h1[n * H1c]);
#pragma unroll
        for (int r = 0; r < 8; r++) {
            float4 t4 = hp[r];
            hv[r*4+0]=t4.x; hv[r*4+1]=t4.y; hv[r*4+2]=t4.z; hv[r*4+3]=t4.w;
        }
        const float4* ap = (const float4*)(&g_agg2[n * H2c + h * 8]);
        float4 a0 = ap[0], a1 = ap[1];
        float ag[8] = {a0.x,a0.y,a0.z,a0.w,a1.x,a1.y,a1.z,a1.w};
#pragma unroll
        for (int oo = 0; oo < 8; oo++) {
            int o = h * 8 + oo;
            float t = sb[o] + ag[oo];
#pragma unroll
            for (int i = 0; i < H1c; i++) t += hv[i] * sw[i * H2c + o];
            v[oo] = fmaxf(t, 0.f);
        }
    }
    const unsigned m = 0xffffffffu;
    int b0 = __shfl_sync(m, b, 0);
    if (__all_sync(m, valid && (b == b0))) {
        // parity-preserving reduce: sums the 16 nodes, keeps halves separate
#pragma unroll
        for (int d = 16; d >= 2; d >>= 1)
#pragma unroll
            for (int o = 0; o < 8; o++) v[o] += __shfl_xor_sync(m, v[o], d);
        if ((tid & 31) < 2) {
#pragma unroll
            for (int o = 0; o < 8; o++)
                atomicAdd(&g_h2sum[b0 * H2c + h * 8 + o], v[o]);
        }
    } else if (valid) {
#pragma unroll
        for (int o = 0; o < 8; o++)
            atomicAdd(&g_h2sum[b * H2c + h * 8 + o], v[o]);
    }
}

// ---------------- final head per graph ----------------------------------------
__global__ void k_final(float* __restrict__ out,
                        const float* __restrict__ wl1, const float* __restrict__ bl1,
                        const float* __restrict__ wl2, const float* __restrict__ bl2) {
    int g = blockIdx.x * blockDim.x + threadIdx.x;
    if (g >= Gg) return;
    float cnt = fmaxf(g_cnt[g], 1.f);
    float s = g_s[g];
    float invs = (s > 0.f) ? (1.f / s) : 0.f;
    float z[H2c + FN];
#pragma unroll
    for (int o = 0; o < H2c; o++) z[o] = g_h2sum[g * H2c + o] / cnt;
#pragma unroll
    for (int f = 0; f < FN; f++) z[H2c + f] = g_num[g * FN + f] * invs;
    float y[8];
#pragma unroll
    for (int j = 0; j < 8; j++) {
        float v = __ldg(&bl1[j]);
#pragma unroll
        for (int c = 0; c < H2c + FN; c++) v += z[c] * __ldg(&wl1[c * 8 + j]);
        y[j] = v;
    }
    float r = __ldg(&bl2[0]);
#pragma unroll
    for (int j = 0; j < 8; j++) r += y[j] * __ldg(&wl2[j]);
    out[g] = r;
}

// ---------------- launch ------------------------------------------------------
extern "C" void kernel_launch(void* const* d_in, const int* in_sizes, int n_in,
                              void* d_out, int out_size) {
    const float* x       = (const float*)d_in[0];
    const float* ea      = (const float*)d_in[1];
    const float* w_e1a   = (const float*)d_in[2];
    const float* b_e1a   = (const float*)d_in[3];
    const float* w_e1b   = (const float*)d_in[4];
    const float* b_e1b   = (const float*)d_in[5];
    const float* w_root1 = (const float*)d_in[6];
    const float* b_root1 = (const float*)d_in[7];
    const float* w_e2a   = (const float*)d_in[8];
    const float* b_e2a   = (const float*)d_in[9];
    const float* w_e2b   = (const float*)d_in[10];
    const float* b_e2b   = (const float*)d_in[11];
    const float* w_root2 = (const float*)d_in[12];
    const float* b_root2 = (const float*)d_in[13];
    const float* w_g1    = (const float*)d_in[14];
    const float* b_g1    = (const float*)d_in[15];
    const float* w_g2    = (const float*)d_in[16];
    const float* b_g2    = (const float*)d_in[17];
    const float* w_l1    = (const float*)d_in[18];
    const float* b_l1    = (const float*)d_in[19];
    const float* w_l2    = (const float*)d_in[20];
    const float* b_l2    = (const float*)d_in[21];
    const int*   ei      = (const int*)d_in[22];
    const int*   batch   = (const int*)d_in[23];
    float* out = (float*)d_out;

    int nblk  = (Nn + 255) / 256;
    int nblk2 = (2 * Nn + 255) / 256;
    k_gate<<<nblk, 256>>>(x, w_g1, b_g1, w_g2, b_g2);
    k_fused1<<<EBLK + ABLK, 128>>>(x, ea, w_e1a, b_e1a, w_e1b, b_e1b, ei, batch);
    k_node1<<<nblk2, 256>>>(x, w_root1, b_root1);
    k_conv2<<<EBLK, 128>>>(ea, w_e2a, b_e2a, w_e2b, b_e2b, ei);
    k_node2<<<nblk2, 256>>>(w_root2, b_root2, batch);
    k_final<<<(Gg + 255) / 256, 256>>>(out, w_l1, b_l1, w_l2, b_l2);
}